// round 1
// baseline (speedup 1.0000x reference)
#include <cuda_runtime.h>
#include <math.h>

// ---------------- problem constants ----------------
#define DM    1024          // d_model
#define DI    2048          // d_inner
#define DS    16            // d_state
#define RK    64            // dt_rank
#define BSZ   2
#define LSEQ  2048
#define TT    (BSZ*LSEQ)    // 4096 tokens
#define XZLD  (2*DI)        // 4096, xz row stride
#define XDBL_LD 96          // dt_rank + 2*d_state

// ---------------- scratch (static device memory; no allocs allowed) ------
__device__ float g_xn  [TT*DM];     // 16 MB  layernorm output
__device__ float g_xz  [TT*XZLD];   // 64 MB  in_proj output (x | z)
__device__ float g_xc  [TT*DI];     // 32 MB  conv+silu output
__device__ float g_xdbl[TT*XDBL_LD];// 1.5 MB x_proj output (dt_r | B | C)
__device__ float g_dt  [TT*DI];     // 32 MB  softplus(dt)
__device__ float g_y   [TT*DI];     // 32 MB  scan output (gated)

// ---------------- helpers ----------------
__device__ __forceinline__ float siluf(float v) {
    return v * __fdividef(1.f, 1.f + __expf(-v));
}

// ---------------- 1) layernorm: one block per token ----------------
__global__ __launch_bounds__(256) void ln_kernel(
    const float* __restrict__ seq, const float* __restrict__ gam,
    const float* __restrict__ bet, float* __restrict__ out)
{
    int t   = blockIdx.x;
    int tid = threadIdx.x;
    const float4 v = reinterpret_cast<const float4*>(seq + (size_t)t*DM)[tid];
    float s = v.x + v.y + v.z + v.w;
    float q = v.x*v.x + v.y*v.y + v.z*v.z + v.w*v.w;
    #pragma unroll
    for (int o = 16; o > 0; o >>= 1) {
        s += __shfl_down_sync(0xffffffffu, s, o);
        q += __shfl_down_sync(0xffffffffu, q, o);
    }
    __shared__ float ss[8], sq[8];
    int wid = tid >> 5;
    if ((tid & 31) == 0) { ss[wid] = s; sq[wid] = q; }
    __syncthreads();
    float S = 0.f, Q = 0.f;
    #pragma unroll
    for (int i = 0; i < 8; i++) { S += ss[i]; Q += sq[i]; }
    float mu  = S * (1.f/DM);
    float var = Q * (1.f/DM) - mu*mu;
    float inv = rsqrtf(var + 1e-5f);
    const float4 g4 = reinterpret_cast<const float4*>(gam)[tid];
    const float4 b4 = reinterpret_cast<const float4*>(bet)[tid];
    float4 o4;
    o4.x = (v.x - mu)*inv*g4.x + b4.x;
    o4.y = (v.y - mu)*inv*g4.y + b4.y;
    o4.z = (v.z - mu)*inv*g4.z + b4.z;
    o4.w = (v.w - mu)*inv*g4.w + b4.w;
    reinterpret_cast<float4*>(out + (size_t)t*DM)[tid] = o4;
}

// ---------------- 2) generic tiled GEMM: C[m][n] = sum_k A[m][k]*W[n][k] ---
// 64x64 tile, BK=16, 256 threads, 4x4 micro-tile per thread.
// EPI: 0 = plain, 1 = softplus(acc + bias[n]), 2 = resid[m*ldc+n] + rs*acc
template<int EPI>
__global__ __launch_bounds__(256) void gemm_kernel(
    const float* __restrict__ A, int lda,
    const float* __restrict__ W, int ldw,
    int N, int K,
    float* __restrict__ C, int ldc,
    const float* __restrict__ bias,
    const float* __restrict__ resid,
    const float* __restrict__ rs_ptr)
{
    __shared__ __align__(16) float As[16][64];
    __shared__ __align__(16) float Ws[16][64];
    int tid = threadIdx.x;
    int m0 = blockIdx.y * 64, n0 = blockIdx.x * 64;
    int lr = tid >> 2;            // 0..63 row of tile
    int lq = (tid & 3) * 4;       // 0,4,8,12 col quad
    int tx = tid & 15, ty = tid >> 4;

    float acc[4][4];
    #pragma unroll
    for (int i = 0; i < 4; i++)
        #pragma unroll
        for (int j = 0; j < 4; j++) acc[i][j] = 0.f;

    const float* Ap = A + (size_t)(m0 + lr) * lda + lq;
    bool wvalid = (n0 + lr) < N;
    const float* Wp = W + (size_t)(wvalid ? (n0 + lr) : 0) * ldw + lq;

    for (int k0 = 0; k0 < K; k0 += 16) {
        float4 av = *reinterpret_cast<const float4*>(Ap + k0);
        float4 wv = wvalid ? *reinterpret_cast<const float4*>(Wp + k0)
                           : make_float4(0.f, 0.f, 0.f, 0.f);
        As[lq+0][lr] = av.x; As[lq+1][lr] = av.y;
        As[lq+2][lr] = av.z; As[lq+3][lr] = av.w;
        Ws[lq+0][lr] = wv.x; Ws[lq+1][lr] = wv.y;
        Ws[lq+2][lr] = wv.z; Ws[lq+3][lr] = wv.w;
        __syncthreads();
        #pragma unroll
        for (int k = 0; k < 16; k++) {
            float4 a = *reinterpret_cast<const float4*>(&As[k][ty*4]);
            float4 b = *reinterpret_cast<const float4*>(&Ws[k][tx*4]);
            acc[0][0] += a.x*b.x; acc[0][1] += a.x*b.y; acc[0][2] += a.x*b.z; acc[0][3] += a.x*b.w;
            acc[1][0] += a.y*b.x; acc[1][1] += a.y*b.y; acc[1][2] += a.y*b.z; acc[1][3] += a.y*b.w;
            acc[2][0] += a.z*b.x; acc[2][1] += a.z*b.y; acc[2][2] += a.z*b.z; acc[2][3] += a.z*b.w;
            acc[3][0] += a.w*b.x; acc[3][1] += a.w*b.y; acc[3][2] += a.w*b.z; acc[3][3] += a.w*b.w;
        }
        __syncthreads();
    }

    float rs = (EPI == 2) ? rs_ptr[0] : 0.f;
    int nb = n0 + tx*4;
    if (nb < N) {
        #pragma unroll
        for (int i = 0; i < 4; i++) {
            int m = m0 + ty*4 + i;
            float4 o;
            if (EPI == 0) {
                o.x = acc[i][0]; o.y = acc[i][1]; o.z = acc[i][2]; o.w = acc[i][3];
            } else if (EPI == 1) {
                #pragma unroll
                for (int j = 0; j < 4; j++) {
                    float v = acc[i][j] + bias[nb + j];
                    float r = (v > 20.f) ? v : log1pf(__expf(v));
                    ((float*)&o)[j] = r;
                }
            } else {
                const float4 r4 = *reinterpret_cast<const float4*>(&resid[(size_t)m*ldc + nb]);
                o.x = r4.x + rs*acc[i][0]; o.y = r4.y + rs*acc[i][1];
                o.z = r4.z + rs*acc[i][2]; o.w = r4.w + rs*acc[i][3];
            }
            *reinterpret_cast<float4*>(&C[(size_t)m*ldc + nb]) = o;
        }
    }
}

// ---------------- 3) causal depthwise conv (D_CONV=4) + bias + SiLU -------
// reads x-half of g_xz (stride XZLD), writes g_xc (stride DI)
__global__ __launch_bounds__(256) void conv_silu_kernel(
    const float* __restrict__ xz, const float* __restrict__ cw,
    const float* __restrict__ cb, float* __restrict__ out)
{
    int gid = blockIdx.x * 256 + threadIdx.x;   // over TT * DI/4
    int t = gid / (DI/4);
    int d = (gid % (DI/4)) * 4;
    int l = t % LSEQ;

    const float4 w0 = reinterpret_cast<const float4*>(cw)[d+0];
    const float4 w1 = reinterpret_cast<const float4*>(cw)[d+1];
    const float4 w2 = reinterpret_cast<const float4*>(cw)[d+2];
    const float4 w3 = reinterpret_cast<const float4*>(cw)[d+3];
    float4 acc = reinterpret_cast<const float4*>(cb)[d >> 2];

    // taps k=0..3 read x[l+k-3]
    #pragma unroll
    for (int k = 0; k < 4; k++) {
        int ls = l + k - 3;
        if (ls >= 0) {
            const float4 xv = *reinterpret_cast<const float4*>(
                &xz[(size_t)(t + k - 3) * XZLD + d]);
            float a0 = (k==0)?w0.x:(k==1)?w0.y:(k==2)?w0.z:w0.w;
            float a1 = (k==0)?w1.x:(k==1)?w1.y:(k==2)?w1.z:w1.w;
            float a2 = (k==0)?w2.x:(k==1)?w2.y:(k==2)?w2.z:w2.w;
            float a3 = (k==0)?w3.x:(k==1)?w3.y:(k==2)?w3.z:w3.w;
            acc.x += xv.x*a0; acc.y += xv.y*a1;
            acc.z += xv.z*a2; acc.w += xv.w*a3;
        }
    }
    acc.x = siluf(acc.x); acc.y = siluf(acc.y);
    acc.z = siluf(acc.z); acc.w = siluf(acc.w);
    *reinterpret_cast<float4*>(&out[(size_t)t*DI + d]) = acc;
}

// ---------------- 4) selective scan -----------------
// lane-per-state layout: 16 lanes per channel, 2 channels per warp.
// 2048 warps total. Writes gated output y = (scan + D*x) * silu(z).
__global__ __launch_bounds__(128) void scan_kernel(
    const float* __restrict__ dt, const float* __restrict__ xc,
    const float* __restrict__ xdbl, const float* __restrict__ xz,
    const float* __restrict__ A_log, const float* __restrict__ Dp,
    float* __restrict__ y)
{
    int warp = (blockIdx.x * 128 + threadIdx.x) >> 5;  // 0..2047
    int lane = threadIdx.x & 31;
    int half = lane >> 4;
    int s    = lane & 15;
    int b    = warp >> 10;                  // DI/2 = 1024 pairs per batch
    int ch   = ((warp & 1023) << 1) + half; // 0..2047

    float Aval = -expf(A_log[ch*DS + s]);
    float Dv   = Dp[ch];

    const float* dtp = dt   + (size_t)b*LSEQ*DI + ch;
    const float* xp  = xc   + (size_t)b*LSEQ*DI + ch;
    const float* zp  = xz   + (size_t)b*LSEQ*XZLD + DI + ch;
    const float* bp  = xdbl + (size_t)b*LSEQ*XDBL_LD + RK + s;
    const float* cp  = bp + DS;
    float*       yp  = y    + (size_t)b*LSEQ*DI + ch;

    float h = 0.f;
    for (int l = 0; l < LSEQ; l++) {
        float dtv = *dtp;
        float xv  = *xp;
        float Bv  = *bp;
        float Cv  = *cp;
        float dA  = __expf(dtv * Aval);
        h = fmaf(h, dA, dtv * xv * Bv);
        float acc = h * Cv;
        acc += __shfl_xor_sync(0xffffffffu, acc, 1);
        acc += __shfl_xor_sync(0xffffffffu, acc, 2);
        acc += __shfl_xor_sync(0xffffffffu, acc, 4);
        acc += __shfl_xor_sync(0xffffffffu, acc, 8);
        if (s == 0) {
            float zv = *zp;
            yp[0] = (acc + Dv * xv) * siluf(zv);
        }
        dtp += DI; xp += DI; zp += XZLD; bp += XDBL_LD; cp += XDBL_LD; yp += DI;
    }
}

// ---------------- launcher ----------------
extern "C" void kernel_launch(void* const* d_in, const int* in_sizes, int n_in,
                              void* d_out, int out_size)
{
    const float* seq       = (const float*)d_in[0];
    const float* ln_g      = (const float*)d_in[1];
    const float* ln_b      = (const float*)d_in[2];
    const float* in_proj_w = (const float*)d_in[3];
    const float* conv_w    = (const float*)d_in[4];
    const float* conv_b    = (const float*)d_in[5];
    const float* x_proj_w  = (const float*)d_in[6];
    const float* dt_proj_w = (const float*)d_in[7];
    const float* dt_proj_b = (const float*)d_in[8];
    const float* A_log     = (const float*)d_in[9];
    const float* Dp        = (const float*)d_in[10];
    const float* out_proj_w= (const float*)d_in[11];
    const float* res_scale = (const float*)d_in[12];
    float* out = (float*)d_out;

    float *xn, *xz, *xc, *xdbl, *dt, *y;
    cudaGetSymbolAddress((void**)&xn,   g_xn);
    cudaGetSymbolAddress((void**)&xz,   g_xz);
    cudaGetSymbolAddress((void**)&xc,   g_xc);
    cudaGetSymbolAddress((void**)&xdbl, g_xdbl);
    cudaGetSymbolAddress((void**)&dt,   g_dt);
    cudaGetSymbolAddress((void**)&y,    g_y);

    // 1) layernorm
    ln_kernel<<<TT, 256>>>(seq, ln_g, ln_b, xn);

    // 2) in_proj: xz[4096 x 4096] = xn[4096x1024] @ in_proj_w[4096x1024]^T
    gemm_kernel<0><<<dim3(XZLD/64, TT/64), 256>>>(
        xn, DM, in_proj_w, DM, XZLD, DM, xz, XZLD, nullptr, nullptr, nullptr);

    // 3) conv + silu on x-half
    conv_silu_kernel<<<(TT*(DI/4))/256, 256>>>(xz, conv_w, conv_b, xc);

    // 4) x_proj: xdbl[4096 x 96] = xc @ x_proj_w[96x2048]^T
    gemm_kernel<0><<<dim3(2, TT/64), 256>>>(
        xc, DI, x_proj_w, DI, XDBL_LD, DI, xdbl, XDBL_LD, nullptr, nullptr, nullptr);

    // 5) dt: dt[4096 x 2048] = softplus(xdbl[:, :64] @ dt_proj_w[2048x64]^T + b)
    gemm_kernel<1><<<dim3(DI/64, TT/64), 256>>>(
        xdbl, XDBL_LD, dt_proj_w, RK, DI, RK, dt, DI, dt_proj_b, nullptr, nullptr);

    // 6) selective scan + gating
    scan_kernel<<<(BSZ*DI/2)*32/128, 128>>>(dt, xc, xdbl, xz, A_log, Dp, y);

    // 7) out_proj + residual: out = seq + rs * (y @ out_proj_w[1024x2048]^T)
    gemm_kernel<2><<<dim3(DM/64, TT/64), 256>>>(
        y, DI, out_proj_w, DI, DM, DI, out, DM, nullptr, seq, res_scale);
}

// round 3
// speedup vs baseline: 2.3840x; 2.3840x over previous
#include <cuda_runtime.h>
#include <cuda_bf16.h>
#include <math.h>
#include <stdint.h>

// ---------------- problem constants ----------------
#define DM    1024          // d_model
#define DI    2048          // d_inner
#define DS    16            // d_state
#define RK    64            // dt_rank
#define BSZ   2
#define LSEQ  2048
#define TT    (BSZ*LSEQ)    // 4096 tokens
#define XZLD  (2*DI)        // 4096, xz row stride
#define XDBL_LD 96          // dt_rank + 2*d_state

// ---------------- scratch (static device memory; no allocs allowed) ------
__device__ __nv_bfloat16 g_xn_bf [TT*DM];       // 8 MB  layernorm output (bf16)
__device__ float         g_xz    [TT*XZLD];     // 64 MB in_proj output (x | z)
__device__ float         g_xc    [TT*DI];       // 32 MB conv+silu output (fp32 for scan)
__device__ __nv_bfloat16 g_xc_bf [TT*DI];       // 16 MB conv+silu output (bf16 for x_proj)
__device__ float         g_xdbl  [TT*XDBL_LD];  // 1.5 MB x_proj output (dt_r | B | C)
__device__ float         g_dt    [TT*DI];       // 32 MB softplus(dt)
__device__ __nv_bfloat16 g_y_bf  [TT*DI];       // 16 MB scan output (gated, bf16)
__device__ __nv_bfloat16 g_win_bf [XZLD*DM];    // 8 MB  in_proj_w bf16
__device__ __nv_bfloat16 g_wout_bf[DM*DI];      // 4 MB  out_proj_w bf16
__device__ __nv_bfloat16 g_wxp_bf [128*DI];     // 512KB x_proj_w bf16, padded 96->128 rows

// ---------------- helpers ----------------
__device__ __forceinline__ float siluf(float v) {
    return v * __fdividef(1.f, 1.f + __expf(-v));
}

__device__ __forceinline__ uint32_t smem_u32(const void* p) {
    uint32_t a;
    asm("{ .reg .u64 t; cvta.to.shared.u64 t, %1; cvt.u32.u64 %0, t; }" : "=r"(a) : "l"(p));
    return a;
}

#define CP16(dst, src) \
    asm volatile("cp.async.cg.shared.global [%0], [%1], 16;" :: "r"(dst), "l"(src))
#define CP_COMMIT() asm volatile("cp.async.commit_group;")
#define CP_WAIT1()  asm volatile("cp.async.wait_group 1;")
#define CP_WAIT0()  asm volatile("cp.async.wait_group 0;")

#define LDSM_X4(r0, r1, r2, r3, addr) \
    asm volatile("ldmatrix.sync.aligned.m8n8.x4.shared.b16 {%0,%1,%2,%3}, [%4];" \
        : "=r"(r0), "=r"(r1), "=r"(r2), "=r"(r3) : "r"(addr))

#define MMA16816(d, a, b) \
    asm volatile("mma.sync.aligned.m16n8k16.row.col.f32.bf16.bf16.f32 " \
        "{%0,%1,%2,%3}, {%4,%5,%6,%7}, {%8,%9}, {%0,%1,%2,%3};" \
        : "+f"((d)[0]), "+f"((d)[1]), "+f"((d)[2]), "+f"((d)[3]) \
        : "r"((a)[0]), "r"((a)[1]), "r"((a)[2]), "r"((a)[3]), \
          "r"((b)[0]), "r"((b)[1]))

// ================== bf16 HMMA GEMM: C[m][n] = sum_k A[m][k]*B[n][k] =======
// CTA tile 128x128, BK=32, 256 threads (8 warps, 2x4 -> warp tile 64x32).
// SMEM rows padded to 80B pitch -> ldmatrix conflict-free. cp.async double buf.
// EPI: 0 = plain fp32 store, 2 = resid + rs*acc, 3 = store only cols < Nreal
#define PITCH 80
#define ABUF  10240                 // 128 rows * 80B
#define SOFF_B (2*ABUF)

template<int EPI>
__global__ __launch_bounds__(256) void hgemm(
    const __nv_bfloat16* __restrict__ A, int lda,
    const __nv_bfloat16* __restrict__ B, int ldb,
    int K, float* __restrict__ C, int ldc, int Nreal,
    const float* __restrict__ resid, const float* __restrict__ rs_ptr)
{
    __shared__ __align__(128) char sm[4*ABUF];   // A0 A1 B0 B1
    const int tid  = threadIdx.x;
    const int lane = tid & 31;
    const int w    = tid >> 5;
    const int wm   = w >> 2;        // 0..1
    const int wn   = w & 3;         // 0..3
    const int m0 = blockIdx.y * 128, n0 = blockIdx.x * 128;
    const uint32_t sbase = smem_u32(sm);

    float acc[4][4][4];
    #pragma unroll
    for (int i = 0; i < 4; i++)
        #pragma unroll
        for (int j = 0; j < 4; j++)
            #pragma unroll
            for (int q = 0; q < 4; q++) acc[i][j][q] = 0.f;

    // gmem->smem: 512 16B chunks per operand; thread handles chunks tid, tid+256
    const int r0c = tid >> 2,        c0c = tid & 3;        // chunk tid
    const int r1c = (tid + 256) >> 2, c1c = tid & 3;       // chunk tid+256

    const int niter = K / 32;

    // ---- preload tile 0 ----
    {
        const int k0 = 0;
        CP16(sbase + r0c*PITCH + c0c*16,            A + (size_t)(m0 + r0c)*lda + k0 + c0c*8);
        CP16(sbase + r1c*PITCH + c1c*16,            A + (size_t)(m0 + r1c)*lda + k0 + c1c*8);
        CP16(sbase + SOFF_B + r0c*PITCH + c0c*16,   B + (size_t)(n0 + r0c)*ldb + k0 + c0c*8);
        CP16(sbase + SOFF_B + r1c*PITCH + c1c*16,   B + (size_t)(n0 + r1c)*ldb + k0 + c1c*8);
        CP_COMMIT();
    }

    // hoisted ldmatrix row offsets
    const int a_row = (lane & 15);              // + wm*64 + mi*16
    const int a_chh = (lane >> 4);              // chunk high bit
    const int b_row = (lane & 7) + ((lane >> 4) << 3);   // + wn*32 + np*16
    const int b_chh = (lane >> 3) & 1;

    for (int i = 0; i < niter; i++) {
        const int buf = i & 1;
        if (i + 1 < niter) {
            const int k0 = (i + 1) * 32;
            const uint32_t ao = (1 - buf) * ABUF;
            CP16(sbase + ao + r0c*PITCH + c0c*16,          A + (size_t)(m0 + r0c)*lda + k0 + c0c*8);
            CP16(sbase + ao + r1c*PITCH + c1c*16,          A + (size_t)(m0 + r1c)*lda + k0 + c1c*8);
            CP16(sbase + SOFF_B + ao + r0c*PITCH + c0c*16, B + (size_t)(n0 + r0c)*ldb + k0 + c0c*8);
            CP16(sbase + SOFF_B + ao + r1c*PITCH + c1c*16, B + (size_t)(n0 + r1c)*ldb + k0 + c1c*8);
            CP_COMMIT();
            CP_WAIT1();
        } else {
            CP_WAIT0();
        }
        __syncthreads();

        const uint32_t sA = sbase + buf * ABUF;
        const uint32_t sB = sbase + SOFF_B + buf * ABUF;
        #pragma unroll
        for (int ks = 0; ks < 2; ks++) {
            uint32_t a[4][4], b[4][2];
            #pragma unroll
            for (int mi = 0; mi < 4; mi++) {
                const int row = wm*64 + mi*16 + a_row;
                const int ch  = 2*ks + a_chh;
                LDSM_X4(a[mi][0], a[mi][1], a[mi][2], a[mi][3], sA + row*PITCH + ch*16);
            }
            #pragma unroll
            for (int np = 0; np < 2; np++) {
                const int row = wn*32 + np*16 + b_row;
                const int ch  = 2*ks + b_chh;
                LDSM_X4(b[2*np][0], b[2*np][1], b[2*np+1][0], b[2*np+1][1],
                        sB + row*PITCH + ch*16);
            }
            #pragma unroll
            for (int mi = 0; mi < 4; mi++)
                #pragma unroll
                for (int nj = 0; nj < 4; nj++)
                    MMA16816(acc[mi][nj], a[mi], b[nj]);
        }
        __syncthreads();
    }

    // ---- epilogue: direct fp32 stores (4-lane groups fill 32B sectors) ----
    const float rs = (EPI == 2) ? rs_ptr[0] : 0.f;
    #pragma unroll
    for (int mi = 0; mi < 4; mi++) {
        #pragma unroll
        for (int nj = 0; nj < 4; nj++) {
            const int row = m0 + wm*64 + mi*16 + (lane >> 2);
            const int col = n0 + wn*32 + nj*8 + (lane & 3)*2;
            if (EPI == 3 && col >= Nreal) continue;
            float2 v0 = make_float2(acc[mi][nj][0], acc[mi][nj][1]);
            float2 v1 = make_float2(acc[mi][nj][2], acc[mi][nj][3]);
            if (EPI == 2) {
                const float2 q0 = *(const float2*)(resid + (size_t)row*ldc + col);
                const float2 q1 = *(const float2*)(resid + (size_t)(row+8)*ldc + col);
                v0.x = q0.x + rs*v0.x; v0.y = q0.y + rs*v0.y;
                v1.x = q1.x + rs*v1.x; v1.y = q1.y + rs*v1.y;
            }
            *(float2*)(C + (size_t)row*ldc + col)     = v0;
            *(float2*)(C + (size_t)(row+8)*ldc + col) = v1;
        }
    }
}

// ---------------- fp32 -> bf16 convert (with zero padding) ----------------
__global__ __launch_bounds__(256) void f2bf_pad(
    const float* __restrict__ s, __nv_bfloat16* __restrict__ d, int n_src, int n_dst)
{
    int i = blockIdx.x * 256 + threadIdx.x;
    if (i < n_dst) d[i] = (i < n_src) ? __float2bfloat16(s[i]) : __float2bfloat16(0.f);
}

// ---------------- 1) layernorm -> bf16 ----------------
__global__ __launch_bounds__(256) void ln_kernel(
    const float* __restrict__ seq, const float* __restrict__ gam,
    const float* __restrict__ bet, __nv_bfloat16* __restrict__ out)
{
    int tok = blockIdx.x;
    int tid = threadIdx.x;
    const float4 v = reinterpret_cast<const float4*>(seq + (size_t)tok*DM)[tid];
    float s = v.x + v.y + v.z + v.w;
    float q = v.x*v.x + v.y*v.y + v.z*v.z + v.w*v.w;
    #pragma unroll
    for (int o = 16; o > 0; o >>= 1) {
        s += __shfl_down_sync(0xffffffffu, s, o);
        q += __shfl_down_sync(0xffffffffu, q, o);
    }
    __shared__ float ss[8], sq[8];
    int wid = tid >> 5;
    if ((tid & 31) == 0) { ss[wid] = s; sq[wid] = q; }
    __syncthreads();
    float S = 0.f, Q = 0.f;
    #pragma unroll
    for (int i = 0; i < 8; i++) { S += ss[i]; Q += sq[i]; }
    float mu  = S * (1.f/DM);
    float var = Q * (1.f/DM) - mu*mu;
    float inv = rsqrtf(var + 1e-5f);
    const float4 g4 = reinterpret_cast<const float4*>(gam)[tid];
    const float4 b4 = reinterpret_cast<const float4*>(bet)[tid];
    float4 o4;
    o4.x = (v.x - mu)*inv*g4.x + b4.x;
    o4.y = (v.y - mu)*inv*g4.y + b4.y;
    o4.z = (v.z - mu)*inv*g4.z + b4.z;
    o4.w = (v.w - mu)*inv*g4.w + b4.w;
    __nv_bfloat162* op = reinterpret_cast<__nv_bfloat162*>(out + (size_t)tok*DM);
    op[tid*2+0] = __floats2bfloat162_rn(o4.x, o4.y);
    op[tid*2+1] = __floats2bfloat162_rn(o4.z, o4.w);
}

// ---------------- SIMT GEMM (kept for dt_proj, K=64) ----------------
template<int EPI>
__global__ __launch_bounds__(256) void gemm_kernel(
    const float* __restrict__ A, int lda,
    const float* __restrict__ W, int ldw,
    int N, int K,
    float* __restrict__ C, int ldc,
    const float* __restrict__ bias)
{
    __shared__ __align__(16) float As[16][64];
    __shared__ __align__(16) float Ws[16][64];
    int tid = threadIdx.x;
    int m0 = blockIdx.y * 64, n0 = blockIdx.x * 64;
    int lr = tid >> 2;
    int lq = (tid & 3) * 4;
    int tx = tid & 15, ty = tid >> 4;

    float acc[4][4];
    #pragma unroll
    for (int i = 0; i < 4; i++)
        #pragma unroll
        for (int j = 0; j < 4; j++) acc[i][j] = 0.f;

    const float* Ap = A + (size_t)(m0 + lr) * lda + lq;
    const float* Wp = W + (size_t)(n0 + lr) * ldw + lq;

    for (int k0 = 0; k0 < K; k0 += 16) {
        float4 av = *reinterpret_cast<const float4*>(Ap + k0);
        float4 wv = *reinterpret_cast<const float4*>(Wp + k0);
        As[lq+0][lr] = av.x; As[lq+1][lr] = av.y;
        As[lq+2][lr] = av.z; As[lq+3][lr] = av.w;
        Ws[lq+0][lr] = wv.x; Ws[lq+1][lr] = wv.y;
        Ws[lq+2][lr] = wv.z; Ws[lq+3][lr] = wv.w;
        __syncthreads();
        #pragma unroll
        for (int k = 0; k < 16; k++) {
            float4 a = *reinterpret_cast<const float4*>(&As[k][ty*4]);
            float4 b = *reinterpret_cast<const float4*>(&Ws[k][tx*4]);
            acc[0][0] += a.x*b.x; acc[0][1] += a.x*b.y; acc[0][2] += a.x*b.z; acc[0][3] += a.x*b.w;
            acc[1][0] += a.y*b.x; acc[1][1] += a.y*b.y; acc[1][2] += a.y*b.z; acc[1][3] += a.y*b.w;
            acc[2][0] += a.z*b.x; acc[2][1] += a.z*b.y; acc[2][2] += a.z*b.z; acc[2][3] += a.z*b.w;
            acc[3][0] += a.w*b.x; acc[3][1] += a.w*b.y; acc[3][2] += a.w*b.z; acc[3][3] += a.w*b.w;
        }
        __syncthreads();
    }

    int nb = n0 + tx*4;
    #pragma unroll
    for (int i = 0; i < 4; i++) {
        int m = m0 + ty*4 + i;
        float4 o;
        if (EPI == 1) {
            #pragma unroll
            for (int j = 0; j < 4; j++) {
                float v = acc[i][j] + bias[nb + j];
                float r = (v > 20.f) ? v : log1pf(__expf(v));
                ((float*)&o)[j] = r;
            }
        } else {
            o.x = acc[i][0]; o.y = acc[i][1]; o.z = acc[i][2]; o.w = acc[i][3];
        }
        *reinterpret_cast<float4*>(&C[(size_t)m*ldc + nb]) = o;
    }
}

// ---------------- 3) causal depthwise conv + bias + SiLU (fp32 + bf16 out) --
__global__ __launch_bounds__(256) void conv_silu_kernel(
    const float* __restrict__ xz, const float* __restrict__ cw,
    const float* __restrict__ cb, float* __restrict__ out,
    __nv_bfloat16* __restrict__ out_bf)
{
    int gid = blockIdx.x * 256 + threadIdx.x;
    int t = gid / (DI/4);
    int d = (gid % (DI/4)) * 4;
    int l = t % LSEQ;

    const float4 w0 = reinterpret_cast<const float4*>(cw)[d+0];
    const float4 w1 = reinterpret_cast<const float4*>(cw)[d+1];
    const float4 w2 = reinterpret_cast<const float4*>(cw)[d+2];
    const float4 w3 = reinterpret_cast<const float4*>(cw)[d+3];
    float4 acc = reinterpret_cast<const float4*>(cb)[d >> 2];

    #pragma unroll
    for (int k = 0; k < 4; k++) {
        int ls = l + k - 3;
        if (ls >= 0) {
            const float4 xv = *reinterpret_cast<const float4*>(
                &xz[(size_t)(t + k - 3) * XZLD + d]);
            float a0 = (k==0)?w0.x:(k==1)?w0.y:(k==2)?w0.z:w0.w;
            float a1 = (k==0)?w1.x:(k==1)?w1.y:(k==2)?w1.z:w1.w;
            float a2 = (k==0)?w2.x:(k==1)?w2.y:(k==2)?w2.z:w2.w;
            float a3 = (k==0)?w3.x:(k==1)?w3.y:(k==2)?w3.z:w3.w;
            acc.x += xv.x*a0; acc.y += xv.y*a1;
            acc.z += xv.z*a2; acc.w += xv.w*a3;
        }
    }
    acc.x = siluf(acc.x); acc.y = siluf(acc.y);
    acc.z = siluf(acc.z); acc.w = siluf(acc.w);
    *reinterpret_cast<float4*>(&out[(size_t)t*DI + d]) = acc;
    __nv_bfloat162* bp = reinterpret_cast<__nv_bfloat162*>(out_bf + (size_t)t*DI + d);
    bp[0] = __floats2bfloat162_rn(acc.x, acc.y);
    bp[1] = __floats2bfloat162_rn(acc.z, acc.w);
}

// ---------------- 4) selective scan (writes gated bf16 y) -----------------
__global__ __launch_bounds__(128) void scan_kernel(
    const float* __restrict__ dt, const float* __restrict__ xc,
    const float* __restrict__ xdbl, const float* __restrict__ xz,
    const float* __restrict__ A_log, const float* __restrict__ Dp,
    __nv_bfloat16* __restrict__ y)
{
    int warp = (blockIdx.x * 128 + threadIdx.x) >> 5;
    int lane = threadIdx.x & 31;
    int half = lane >> 4;
    int s    = lane & 15;
    int b    = warp >> 10;
    int ch   = ((warp & 1023) << 1) + half;

    float Aval = -expf(A_log[ch*DS + s]);
    float Dv   = Dp[ch];

    const float* dtp = dt   + (size_t)b*LSEQ*DI + ch;
    const float* xp  = xc   + (size_t)b*LSEQ*DI + ch;
    const float* zp  = xz   + (size_t)b*LSEQ*XZLD + DI + ch;
    const float* bp  = xdbl + (size_t)b*LSEQ*XDBL_LD + RK + s;
    const float* cp  = bp + DS;
    __nv_bfloat16* yp = y   + (size_t)b*LSEQ*DI + ch;

    float h = 0.f;
    for (int l = 0; l < LSEQ; l++) {
        float dtv = *dtp;
        float xv  = *xp;
        float Bv  = *bp;
        float Cv  = *cp;
        float dA  = __expf(dtv * Aval);
        h = fmaf(h, dA, dtv * xv * Bv);
        float acc = h * Cv;
        acc += __shfl_xor_sync(0xffffffffu, acc, 1);
        acc += __shfl_xor_sync(0xffffffffu, acc, 2);
        acc += __shfl_xor_sync(0xffffffffu, acc, 4);
        acc += __shfl_xor_sync(0xffffffffu, acc, 8);
        if (s == 0) {
            float zv = *zp;
            yp[0] = __float2bfloat16((acc + Dv * xv) * siluf(zv));
        }
        dtp += DI; xp += DI; zp += XZLD; bp += XDBL_LD; cp += XDBL_LD; yp += DI;
    }
}

// ---------------- launcher ----------------
extern "C" void kernel_launch(void* const* d_in, const int* in_sizes, int n_in,
                              void* d_out, int out_size)
{
    const float* seq       = (const float*)d_in[0];
    const float* ln_g      = (const float*)d_in[1];
    const float* ln_b      = (const float*)d_in[2];
    const float* in_proj_w = (const float*)d_in[3];
    const float* conv_w    = (const float*)d_in[4];
    const float* conv_b    = (const float*)d_in[5];
    const float* x_proj_w  = (const float*)d_in[6];
    const float* dt_proj_w = (const float*)d_in[7];
    const float* dt_proj_b = (const float*)d_in[8];
    const float* A_log     = (const float*)d_in[9];
    const float* Dp        = (const float*)d_in[10];
    const float* out_proj_w= (const float*)d_in[11];
    const float* res_scale = (const float*)d_in[12];
    float* out = (float*)d_out;

    __nv_bfloat16 *xn_bf, *xc_bf, *y_bf, *win_bf, *wout_bf, *wxp_bf;
    float *xz, *xc, *xdbl, *dt;
    cudaGetSymbolAddress((void**)&xn_bf,  g_xn_bf);
    cudaGetSymbolAddress((void**)&xz,     g_xz);
    cudaGetSymbolAddress((void**)&xc,     g_xc);
    cudaGetSymbolAddress((void**)&xc_bf,  g_xc_bf);
    cudaGetSymbolAddress((void**)&xdbl,   g_xdbl);
    cudaGetSymbolAddress((void**)&dt,     g_dt);
    cudaGetSymbolAddress((void**)&y_bf,   g_y_bf);
    cudaGetSymbolAddress((void**)&win_bf, g_win_bf);
    cudaGetSymbolAddress((void**)&wout_bf,g_wout_bf);
    cudaGetSymbolAddress((void**)&wxp_bf, g_wxp_bf);

    // 0) weight conversions to bf16
    f2bf_pad<<<(XZLD*DM + 255)/256, 256>>>(in_proj_w,  win_bf,  XZLD*DM, XZLD*DM);
    f2bf_pad<<<(DM*DI   + 255)/256, 256>>>(out_proj_w, wout_bf, DM*DI,   DM*DI);
    f2bf_pad<<<(128*DI  + 255)/256, 256>>>(x_proj_w,   wxp_bf,  XDBL_LD*DI, 128*DI);

    // 1) layernorm -> bf16
    ln_kernel<<<TT, 256>>>(seq, ln_g, ln_b, xn_bf);

    // 2) in_proj (HMMA): xz[4096 x 4096] = xn @ in_proj_w^T
    hgemm<0><<<dim3(XZLD/128, TT/128), 256>>>(
        xn_bf, DM, win_bf, DM, DM, xz, XZLD, XZLD, nullptr, nullptr);

    // 3) conv + silu (fp32 + bf16 outputs)
    conv_silu_kernel<<<(TT*(DI/4))/256, 256>>>(xz, conv_w, conv_b, xc, xc_bf);

    // 4) x_proj (HMMA, N padded 96->128): xdbl[4096 x 96]
    hgemm<3><<<dim3(1, TT/128), 256>>>(
        xc_bf, DI, wxp_bf, DI, DI, xdbl, XDBL_LD, XDBL_LD, nullptr, nullptr);

    // 5) dt = softplus(xdbl[:, :64] @ dt_proj_w^T + b)   (SIMT, K=64)
    gemm_kernel<1><<<dim3(DI/64, TT/64), 256>>>(
        xdbl, XDBL_LD, dt_proj_w, RK, DI, RK, dt, DI, dt_proj_b);

    // 6) selective scan + gating -> bf16 y
    scan_kernel<<<(BSZ*DI/2)*32/128, 128>>>(dt, xc, xdbl, xz, A_log, Dp, y_bf);

    // 7) out_proj (HMMA) + residual: out = seq + rs * (y @ out_proj_w^T)
    hgemm<2><<<dim3(DM/128, TT/128), 256>>>(
        y_bf, DI, wout_bf, DI, DI, out, DM, DM, seq, res_scale);
}